// round 17
// baseline (speedup 1.0000x reference)
#include <cuda_runtime.h>
#include <cuda_bf16.h>

// ts_std: sliding-window population std over time, per feature.
// x: [B=64, T=2048, F=256] fp32 -> out: [B, S=2017, F] fp32, window=32, stride=1.
//
// R14: float4 vectorization (LDG.128/STG.128) after R13 profile showed
// dram=62.7% with traffic already at the 266MB minimum -> bytes-in-flight
// limited. 64 float4 lanes per row; each 128-thread CTA = two 64-thread
// sub-blocks on adjacent 64-output sub-segments (intra-CTA halo overlap
// hits L1). Grid 64x16 = 1024 CTAs (~7/SM, one wave).
// Two-stream sliding window: "new" caching loads, "old" __ldcs re-reads
// (32 rows back -> L1/L2 hit, no extra DRAM), __stcs stores.
// Incremental sums over <=64 steps: drift ~1e-5 rel vs 1e-3 gate.

#define BB 64
#define TT 2048
#define FF 256
#define WW 32
#define SS (TT - WW + 1)              // 2017
#define SEGC 128                      // outputs per CTA
#define SEGS 64                       // outputs per 64-thread sub-block
#define NSEG ((SS + SEGC - 1) / SEGC) // 16
#define LB 4                          // outputs per fast-path chunk
#define FV4 (FF / 4)                  // float4 lanes per time row = 64

__device__ __forceinline__ void accum(const float4 v, float4& s1, float4& s2) {
    s1.x += v.x; s1.y += v.y; s1.z += v.z; s1.w += v.w;
    s2.x = fmaf(v.x, v.x, s2.x);
    s2.y = fmaf(v.y, v.y, s2.y);
    s2.z = fmaf(v.z, v.z, s2.z);
    s2.w = fmaf(v.w, v.w, s2.w);
}

__device__ __forceinline__ float4 stdval(const float4 s1, const float4 s2,
                                         const float inv_w) {
    float4 o;
    float m, v;
    m = s1.x * inv_w; v = fmaf(-m, m, s2.x * inv_w); o.x = __fsqrt_rn(fmaxf(v, 0.0f));
    m = s1.y * inv_w; v = fmaf(-m, m, s2.y * inv_w); o.y = __fsqrt_rn(fmaxf(v, 0.0f));
    m = s1.z * inv_w; v = fmaf(-m, m, s2.z * inv_w); o.z = __fsqrt_rn(fmaxf(v, 0.0f));
    m = s1.w * inv_w; v = fmaf(-m, m, s2.w * inv_w); o.w = __fsqrt_rn(fmaxf(v, 0.0f));
    return o;
}

__device__ __forceinline__ void slide(const float4 n, const float4 o,
                                      float4& s1, float4& s2) {
    s1.x += n.x - o.x; s1.y += n.y - o.y;
    s1.z += n.z - o.z; s1.w += n.w - o.w;
    s2.x += fmaf(n.x, n.x, -o.x * o.x);
    s2.y += fmaf(n.y, n.y, -o.y * o.y);
    s2.z += fmaf(n.z, n.z, -o.z * o.z);
    s2.w += fmaf(n.w, n.w, -o.w * o.w);
}

__global__ __launch_bounds__(128, 6)
void ts_std_kernel(const float* __restrict__ x, float* __restrict__ out) {
    const int lane = threadIdx.x & 63;   // float4 lane (0..63)
    const int sub  = threadIdx.x >> 6;   // sub-segment within CTA (0 or 1)
    const int b    = blockIdx.x;

    const int s_begin = blockIdx.y * SEGC + sub * SEGS;  // max 1984 < SS
    const int s_end   = min(SS, s_begin + SEGS);

    const float4* __restrict__ xp = (const float4*)(x + b * (TT * FF)) + lane;
    float4* __restrict__       op = (float4*)(out + b * (SS * FF)) + lane;

    const float inv_w = 1.0f / (float)WW;

    // Prime: accumulate rows [s_begin, s_begin+32) in batches of 8 (MLP).
    float4 s1 = make_float4(0.f, 0.f, 0.f, 0.f);
    float4 s2 = make_float4(0.f, 0.f, 0.f, 0.f);
    {
        const float4* __restrict__ p0 = xp + s_begin * FV4;
        #pragma unroll
        for (int jb = 0; jb < WW; jb += 8) {
            float4 t[8];
            #pragma unroll
            for (int k = 0; k < 8; k++) t[k] = p0[(jb + k) * FV4];
            #pragma unroll
            for (int k = 0; k < 8; k++) accum(t[k], s1, s2);
        }
    }

    int s = s_begin;

    // Fast path: LB outputs per chunk; both streams unguarded.
    for (; (s + LB <= s_end) && (s + WW + LB <= TT); s += LB) {
        float4 nxt[LB], old[LB];
        const float4* __restrict__ ldn = xp + (s + WW) * FV4;
        const float4* __restrict__ ldo = xp + s * FV4;
        #pragma unroll
        for (int k = 0; k < LB; k++) nxt[k] = ldn[k * FV4];          // caching
        #pragma unroll
        for (int k = 0; k < LB; k++) old[k] = __ldcs(ldo + k * FV4); // last touch
        float4* __restrict__ st = op + s * FV4;
        #pragma unroll
        for (int k = 0; k < LB; k++) {
            __stcs(st + k * FV4, stdval(s1, s2, inv_w));
            slide(nxt[k], old[k], s1, s2);
        }
    }

    // Tail: one output at a time, guarded update.
    for (; s < s_end; s++) {
        __stcs(op + s * FV4, stdval(s1, s2, inv_w));
        if (s + WW < TT) {
            float4 xn = xp[(s + WW) * FV4];
            float4 xo = __ldcs(xp + s * FV4);
            slide(xn, xo, s1, s2);
        }
    }
}

extern "C" void kernel_launch(void* const* d_in, const int* in_sizes, int n_in,
                              void* d_out, int out_size) {
    const float* x = (const float*)d_in[0];
    float* out = (float*)d_out;
    (void)in_sizes; (void)n_in; (void)out_size;

    dim3 grid(BB, NSEG);
    dim3 block(128);
    ts_std_kernel<<<grid, block>>>(x, out);
}